// round 6
// baseline (speedup 1.0000x reference)
#include <cuda_runtime.h>
#include <cstdint>

// Persistent scratch. Zero at module load; the LAST CTA of every launch drains
// it into d_out and resets it, so every graph replay starts clean.
// Layout: [0..3] counts[k][n] (k*2+n), [4..23] incorrect[t][k][n] (4+t*4+k*2+n)
__device__ int      g_acc[24];
__device__ unsigned g_done = 0;

__global__ __launch_bounds__(256, 3)
void acc_fused(const float* __restrict__ pred,
               const float* __restrict__ ev,
               const int*   __restrict__ emask,
               float* __restrict__ out, int out_n) {
    const int b    = blockIdx.x;
    const int tid  = threadIdx.x;
    const int warp = tid >> 5;
    const int lane = tid & 31;

    __shared__ float    s_dist2[64];
    __shared__ unsigned s_maskbits[2];

    // mask bits: entity_mask[b, e, 0] != 0
    if (warp < 2) {
        const int e = warp * 32 + lane;
        const int m = emask[(size_t)b * 128 + (size_t)e * 2];
        unsigned bits = __ballot_sync(0xffffffffu, m != 0);
        if (lane == 0) s_maskbits[warp] = bits;
    }

    // ---- phase 1: issue ALL 16 LDG.128s before any consumption (MLP ~16) ----
    const float4* evb = reinterpret_cast<const float4*>(ev + (size_t)b * 64 * 256);
    float4 va[8], vc[8];
    #pragma unroll
    for (int i = 0; i < 8; i++) {
        const float4* row = evb + (size_t)(warp + i * 8) * 64;  // entity warp+8i
        va[i] = row[lane];
        vc[i] = row[32 + lane];
    }

    // predicted row (L2/L1-resident after first touch; tiny)
    const float4* p4 = reinterpret_cast<const float4*>(pred + (size_t)b * 256);
    const float4 pA = p4[lane];
    const float4 pB = p4[32 + lane];

    // ---- phase 2: squared-distance partials ----
    float d2[8];
    #pragma unroll
    for (int i = 0; i < 8; i++) {
        float d, s;
        d  = va[i].x - pA.x; s  = d * d;
        d  = va[i].y - pA.y; s += d * d;
        d  = va[i].z - pA.z; s += d * d;
        d  = va[i].w - pA.w; s += d * d;
        d  = vc[i].x - pB.x; s += d * d;
        d  = vc[i].y - pB.y; s += d * d;
        d  = vc[i].z - pB.z; s += d * d;
        d  = vc[i].w - pB.w; s += d * d;
        d2[i] = s;
    }

    // ---- phase 3: warp reductions -> s_dist2[64] ----
    #pragma unroll
    for (int i = 0; i < 8; i++) {
        float s = d2[i];
        #pragma unroll
        for (int off = 16; off > 0; off >>= 1)
            s += __shfl_xor_sync(0xffffffffu, s, off);
        if (lane == 0) s_dist2[warp + i * 8] = s;
    }
    __syncthreads();

    // ---- phase 4: per-row logic + global histogram (warp 0) ----
    if (warp == 0) {
        const unsigned long long mm =
            ((unsigned long long)s_maskbits[1] << 32) | (unsigned long long)s_maskbits[0];
        const bool is_known = (mm & 1ull) != 0ull;

        // neg entities = masked entities with cumsum > 1 == mask minus lowest set bit
        const unsigned long long negbits = (mm != 0ull) ? (mm & (mm - 1ull)) : 0ull;
        const bool has_neg = (negbits != 0ull);

        const float BIG = 3.0e38f;
        float v0 = ((negbits >> lane) & 1ull)        ? s_dist2[lane]      : BIG;
        float v1 = ((negbits >> (lane + 32)) & 1ull) ? s_dist2[lane + 32] : BIG;
        float mn2 = fminf(v0, v1);
        #pragma unroll
        for (int off = 16; off > 0; off >>= 1)
            mn2 = fminf(mn2, __shfl_xor_sync(0xffffffffu, mn2, off));

        if (lane == 0) {
            const float pos2 = s_dist2[0];
            const int cell = (is_known ? 2 : 0) + (has_neg ? 1 : 0);
            atomicAdd(&g_acc[cell], 1);

            // thresholds squared: (0.5,1,1.5,2,3)^2 — monotone in d^2 space
            const float T2[5] = {0.25f, 1.0f, 2.25f, 4.0f, 9.0f};
            #pragma unroll
            for (int t = 0; t < 5; t++) {
                bool flag;
                if (is_known && !has_neg)      flag = (T2[t] < pos2);
                else if (!is_known && has_neg) flag = (mn2 < T2[t]);
                else if (is_known && has_neg)  flag = (fminf(mn2, T2[t]) < pos2);
                else                           flag = false;
                if (flag) atomicAdd(&g_acc[4 + t * 4 + cell], 1);
            }
        }

        // ---- last-CTA finalize: drain scratch into d_out (float32) and reset ----
        __threadfence();
        unsigned ticket = 0;
        if (lane == 0) ticket = atomicAdd(&g_done, 1u);
        ticket = __shfl_sync(0xffffffffu, ticket, 0);
        if (ticket == gridDim.x - 1) {
            if (lane < 24) out[lane] = (float)atomicExch(&g_acc[lane], 0);
            for (int i = 24 + lane; i < out_n; i += 32) out[i] = 0.0f;
            __threadfence();
            if (lane == 0) atomicExch(&g_done, 0u);
        }
    }
}

extern "C" void kernel_launch(void* const* d_in, const int* in_sizes, int n_in,
                              void* d_out, int out_size) {
    // Bind inputs by element count: ev largest; pred = ev/64; mask = ev/128
    long long nev = -1; int iev = 0;
    for (int i = 0; i < n_in; i++)
        if ((long long)in_sizes[i] > nev) { nev = in_sizes[i]; iev = i; }
    int ipred = iev, imask = iev;
    for (int i = 0; i < n_in; i++) {
        if (i == iev) continue;
        if ((long long)in_sizes[i] * 64  == nev) ipred = i;
        if ((long long)in_sizes[i] * 128 == nev) imask = i;
    }

    const float* pred  = (const float*)d_in[ipred];
    const float* ev    = (const float*)d_in[iev];
    const int*   emask = (const int*)d_in[imask];

    const int B = (int)(nev / (64 * 256));

    acc_fused<<<B, 256>>>(pred, ev, emask, (float*)d_out, out_size);
}

// round 7
// speedup vs baseline: 1.0425x; 1.0425x over previous
#include <cuda_runtime.h>
#include <cstdint>

// Persistent scratch. Zero at module load; the LAST CTA of every launch drains
// it into d_out and resets it, so every graph replay starts clean.
// Layout: [0..3] counts[k][n] (k*2+n), [4..23] incorrect[t][k][n] (4+t*4+k*2+n)
__device__ int      g_acc[24];
__device__ unsigned g_done = 0;

__global__ __launch_bounds__(256, 8)
void acc_fused(const float* __restrict__ pred,
               const float* __restrict__ ev,
               const int*   __restrict__ emask,
               float* __restrict__ out, int out_n) {
    const int b    = blockIdx.x;
    const int tid  = threadIdx.x;
    const int warp = tid >> 5;
    const int lane = tid & 31;

    __shared__ float    s_dist2[64];
    __shared__ unsigned s_maskbits[2];

    // mask bits: entity_mask[b, e, 0] != 0
    if (warp < 2) {
        const int e = warp * 32 + lane;
        const int m = emask[(size_t)b * 128 + (size_t)e * 2];
        unsigned bits = __ballot_sync(0xffffffffu, m != 0);
        if (lane == 0) s_maskbits[warp] = bits;
    }

    // predicted row: lane covers [lane*4,+4) and [128+lane*4,+4)
    const float4* p4 = reinterpret_cast<const float4*>(pred + (size_t)b * 256);
    const float4 pA = p4[lane];
    const float4 pB = p4[32 + lane];

    // distances: warp w handles entities w, w+8, ..., w+56.
    // Interleaved load/compute (fits the 32-reg budget at 8 CTAs/SM; ptxas
    // pipelines the streaming loads). Shuffle reductions deferred.
    const float4* evb = reinterpret_cast<const float4*>(ev + (size_t)b * 64 * 256);
    float d2[8];
    #pragma unroll
    for (int i = 0; i < 8; i++) {
        const float4* row = evb + (size_t)(warp + i * 8) * 64;  // entity warp+8i
        const float4 a = __ldcs(row + lane);        // read-once stream: evict-first
        const float4 c = __ldcs(row + 32 + lane);
        float d, s;
        d  = a.x - pA.x; s  = d * d;
        d  = a.y - pA.y; s += d * d;
        d  = a.z - pA.z; s += d * d;
        d  = a.w - pA.w; s += d * d;
        d  = c.x - pB.x; s += d * d;
        d  = c.y - pB.y; s += d * d;
        d  = c.z - pB.z; s += d * d;
        d  = c.w - pB.w; s += d * d;
        d2[i] = s;
    }
    #pragma unroll
    for (int i = 0; i < 8; i++) {
        float s = d2[i];
        #pragma unroll
        for (int off = 16; off > 0; off >>= 1)
            s += __shfl_xor_sync(0xffffffffu, s, off);
        if (lane == 0) s_dist2[warp + i * 8] = s;
    }
    __syncthreads();

    // ---- per-row logic + global histogram (warp 0) ----
    if (warp == 0) {
        const unsigned long long mm =
            ((unsigned long long)s_maskbits[1] << 32) | (unsigned long long)s_maskbits[0];
        const bool is_known = (mm & 1ull) != 0ull;

        // neg entities = masked entities with cumsum > 1 == mask minus lowest set bit
        const unsigned long long negbits = (mm != 0ull) ? (mm & (mm - 1ull)) : 0ull;
        const bool has_neg = (negbits != 0ull);

        const float BIG = 3.0e38f;
        float v0 = ((negbits >> lane) & 1ull)        ? s_dist2[lane]      : BIG;
        float v1 = ((negbits >> (lane + 32)) & 1ull) ? s_dist2[lane + 32] : BIG;
        float mn2 = fminf(v0, v1);
        #pragma unroll
        for (int off = 16; off > 0; off >>= 1)
            mn2 = fminf(mn2, __shfl_xor_sync(0xffffffffu, mn2, off));

        if (lane == 0) {
            const float pos2 = s_dist2[0];
            const int cell = (is_known ? 2 : 0) + (has_neg ? 1 : 0);
            atomicAdd(&g_acc[cell], 1);

            // thresholds squared: (0.5,1,1.5,2,3)^2 — monotone in d^2 space
            const float T2[5] = {0.25f, 1.0f, 2.25f, 4.0f, 9.0f};
            #pragma unroll
            for (int t = 0; t < 5; t++) {
                bool flag;
                if (is_known && !has_neg)      flag = (T2[t] < pos2);
                else if (!is_known && has_neg) flag = (mn2 < T2[t]);
                else if (is_known && has_neg)  flag = (fminf(mn2, T2[t]) < pos2);
                else                           flag = false;
                if (flag) atomicAdd(&g_acc[4 + t * 4 + cell], 1);
            }
        }

        // ---- last-CTA finalize: drain scratch into d_out (float32) and reset ----
        __threadfence();
        unsigned ticket = 0;
        if (lane == 0) ticket = atomicAdd(&g_done, 1u);
        ticket = __shfl_sync(0xffffffffu, ticket, 0);
        if (ticket == gridDim.x - 1) {
            if (lane < 24) out[lane] = (float)atomicExch(&g_acc[lane], 0);
            for (int i = 24 + lane; i < out_n; i += 32) out[i] = 0.0f;
            __threadfence();
            if (lane == 0) atomicExch(&g_done, 0u);
        }
    }
}

extern "C" void kernel_launch(void* const* d_in, const int* in_sizes, int n_in,
                              void* d_out, int out_size) {
    // Bind inputs by element count: ev largest; pred = ev/64; mask = ev/128
    long long nev = -1; int iev = 0;
    for (int i = 0; i < n_in; i++)
        if ((long long)in_sizes[i] > nev) { nev = in_sizes[i]; iev = i; }
    int ipred = iev, imask = iev;
    for (int i = 0; i < n_in; i++) {
        if (i == iev) continue;
        if ((long long)in_sizes[i] * 64  == nev) ipred = i;
        if ((long long)in_sizes[i] * 128 == nev) imask = i;
    }

    const float* pred  = (const float*)d_in[ipred];
    const float* ev    = (const float*)d_in[iev];
    const int*   emask = (const int*)d_in[imask];

    const int B = (int)(nev / (64 * 256));

    acc_fused<<<B, 256>>>(pred, ev, emask, (float*)d_out, out_size);
}